// round 16
// baseline (speedup 1.0000x reference)
#include <cuda_runtime.h>
#include <cstdint>

#define HW      9216            // 96*96
#define NPIX    589824          // 64*HW
#define GPIX    64              // pixels per group
#define NITER   4               // groups per CTA -> 256 consecutive px (256 | 9216)
#define NBLK    (NPIX / (GPIX * NITER))   // 2304
#define NSTAGE  2
#define TILE_F  (81 * GPIX)     // floats per stage
#define TILE_B  (TILE_F * 4)    // 20736 bytes

#define INV_LOG49 0.2569487252483261f
#define INV_LOG81 0.2275598569527368f
#define L2E       1.4426950408889634f

__device__ __forceinline__ float ex2(float x) {
    float y;
    asm("ex2.approx.ftz.f32 %0, %1;" : "=f"(y) : "f"(x));
    return y;
}

__device__ __forceinline__ uint32_t smem_u32(const void* p) {
    uint32_t a;
    asm("{ .reg .u64 t; cvta.to.shared.u64 t, %1; cvt.u32.u64 %0, t; }"
        : "=r"(a) : "l"(p));
    return a;
}

__device__ __forceinline__ void cp16(uint32_t dst, const void* src) {
    asm volatile("cp.async.cg.shared.global [%0], [%1], 16;"
                 :: "r"(dst), "l"(src) : "memory");
}
#define CP_COMMIT() asm volatile("cp.async.commit_group;" ::: "memory")
#define CP_WAIT(N)  asm volatile("cp.async.wait_group %0;" :: "n"(N) : "memory")

struct SmemX {
    float xm[2][GPIX];
    int   xi[2][GPIX];
    float spart[6][2][GPIX];
};

// Single LDS sweep: load role's slice into registers + fused max/argmax
// (2 chains, tie-aware merge -> first occurrence).
template<int START, int CNT>
__device__ __forceinline__ void load_sweep(const float* __restrict__ buf,
                                           float* val, float& M, int& A) {
#pragma unroll
    for (int k = 0; k < CNT; k++)
        val[k] = buf[(START + k) * GPIX];

    float pm0 = val[0];  int pi0 = START;
    float pm1 = val[1];  int pi1 = START + 1;
#pragma unroll
    for (int k = 2; k < CNT; k++) {
        if (k & 1) { if (val[k] > pm1) { pm1 = val[k]; pi1 = START + k; } }
        else       { if (val[k] > pm0) { pm0 = val[k]; pi0 = START + k; } }
    }
    M = pm0; A = pi0;
    if (pm1 > M || (pm1 == M && pi1 < A)) { M = pm1; A = pi1; }
}

// Moments from the register copy, UNNORMALIZED exp (|val|<~6 for N(0,1):
// no overflow; max-shift cancels in softmax ratios and in the entropy form).
template<int START, int CNT>
__device__ __forceinline__ void moments(const float* val,
                                        unsigned rowbits, unsigned colbits,
                                        float* acc) {
#pragma unroll
    for (int k = 0; k < CNT; k++) {
        const int i = START + k;        // compile-time
        const int u = i / 9;
        const int v = i - u * 9;
        float e = ex2(val[k] * L2E);    // exp(val)
        acc[0] += e;                    // Sg
        acc[1]  = fmaf(val[k], e, acc[1]);  // sum val*e
        if ((rowbits >> u) & (colbits >> v) & 1u) {
            acc[2] += e;
            acc[3]  = fmaf(val[k], e, acc[3]);
            acc[4]  = fmaf(e, (float)(u - 4), acc[4]);
            acc[5]  = fmaf(e, (float)(v - 4), acc[5]);
        }
    }
}

__global__ __launch_bounds__(128)
void vcn_kernel(const float* __restrict__ x, float* __restrict__ out) {
    extern __shared__ __align__(16) float dyn[];   // [NSTAGE][81][GPIX]
    __shared__ SmemX sx;

    const int tid  = threadIdx.x;
    const int role = tid >> 6;          // 0: elems 0..40, 1: elems 41..80
    const int p    = tid & 63;          // pixel within group

    // CTA covers GPIX*NITER = 256 consecutive pixels; never crosses a batch.
    const int pixel0 = blockIdx.x * (GPIX * NITER);
    const int b   = pixel0 / HW;
    const int hw0 = pixel0 - b * HW;
    const char* gbase0 = (const char*)(x + (size_t)b * 81 * HW + hw0);
    float*      pout0  = out + (size_t)b * 4 * HW + hw0 + p;   // +p (R10 lesson)

    // cp.async map. Tile = 81 planes x 256B = 1296 16B-chunks; 128 threads take
    // c = tid + j*128 (j=0..9): plane = (tid>>4)+8j, sub = tid&15 (128 ≡ 0 mod 16).
    // Threads 0..15 also take c = 1280+tid (plane 80; goffb == tid*16 there).
    const uint32_t goffb = (uint32_t)(tid >> 4) * (HW * 4) + (uint32_t)(tid & 15) * 16;
    const uint32_t soffb = (uint32_t)tid * 16;
    const uint32_t sdyn  = smem_u32(dyn);

    auto issue = [&](int g, int s) {
        const char* gb  = gbase0 + g * (GPIX * 4) + goffb;
        uint32_t    dst = sdyn + (uint32_t)s * TILE_B + soffb;
#pragma unroll
        for (int j = 0; j < 10; j++)
            cp16(dst + j * 2048u, gb + (size_t)j * 8 * (HW * 4));
        if (tid < 16)
            cp16(dst + 20480u, gb + (size_t)80 * HW * 4);
    };

    // Prologue: group 0 in flight.
    issue(0, 0); CP_COMMIT();

#pragma unroll 1
    for (int g = 0; g < NITER; g++) {
        // Stage (g+1)&1's last readers were iter g-1's LDS loads, sealed B2(g-1).
        if (g + 1 < NITER) {
            issue(g + 1, (g + 1) & 1);
            CP_COMMIT();
            CP_WAIT(1);    // group g complete; g+1 may stay in flight
        } else {
            CP_WAIT(0);
        }
        __syncthreads();                       // B0: tile g visible to all

        const float* buf = dyn + (g & 1) * TILE_F + p;   // elem i at buf[i*GPIX]

        // Single LDS sweep: registers + fused max/argmax (barrier-free branch).
        float val[41];
        float Mh; int Ah;
        if (role == 0) load_sweep< 0, 41>(buf, val, Mh, Ah);
        else           load_sweep<41, 40>(buf, val, Mh, Ah);
        sx.xm[role][p] = Mh;
        sx.xi[role][p] = Ah;
        __syncthreads();                       // B1

        // Cross-role merge: role-A indices all < role-B indices, strict '>'
        // preserves first occurrence.
        const float Ma = sx.xm[0][p];
        const float Mb = sx.xm[1][p];
        const int   amax = (Mb > Ma) ? sx.xi[1][p] : sx.xi[0][p];

        const int iu = amax / 9;
        const int iv = amax - iu * 9;
        const unsigned rowbits = (0x7Fu << iu) >> 3;   // bit u set iff |u-iu|<=3
        const unsigned colbits = (0x7Fu << iv) >> 3;

        // Moments from register copy (no second LDS sweep).
        float acc[6] = {0.f, 0.f, 0.f, 0.f, 0.f, 0.f};
        if (role == 0) moments< 0, 41>(val, rowbits, colbits, acc);
        else           moments<41, 40>(val, rowbits, colbits, acc);
#pragma unroll
        for (int j = 0; j < 6; j++) sx.spart[j][role][p] = acc[j];
        __syncthreads();                       // B2: seals spart (+ stage reads)

        if (role == 0) {
#pragma unroll
            for (int j = 0; j < 6; j++) acc[j] += sx.spart[j][1][p];

            const float Sg = acc[0], Sl = acc[2];
            const float invSl = 1.0f / Sl;
            const float invSg = 1.0f / Sg;
            // -sum p log p = log S - (sum val*e)/S   (unnormalized e)
            const float entl = (__logf(Sl) - acc[3] * invSl) * INV_LOG49;
            const float entg = (__logf(Sg) - acc[1] * invSg) * INV_LOG81;

            float* po = pout0 + g * GPIX;
            po[0]      = acc[4] * invSl;
            po[HW]     = acc[5] * invSl;
            po[2 * HW] = entl;
            po[3 * HW] = entg;
        }
    }
}

extern "C" void kernel_launch(void* const* d_in, const int* in_sizes, int n_in,
                              void* d_out, int out_size) {
    const float* x = (const float*)d_in[0];
    float* out = (float*)d_out;
    cudaFuncSetAttribute(vcn_kernel, cudaFuncAttributeMaxDynamicSharedMemorySize,
                         NSTAGE * TILE_B);
    vcn_kernel<<<NBLK, 128, NSTAGE * TILE_B>>>(x, out);   // 2304 CTAs
}